// round 1
// baseline (speedup 1.0000x reference)
#include <cuda_runtime.h>

// ---------------------------------------------------------------------------
// MeanAggregator: out[r, :] = mean over edges e with row_ids[e]==r of
//                 features[neigh_ids[e], :]   (row_ids sorted ascending)
//
// Inputs (metadata order):
//   d_in[0] = features  float32  [N_NODES * 128]
//   d_in[1] = neigh_ids int64 or int32 (jax x64 ambiguity -> runtime detect)
//   d_in[2] = row_ids   same dtype, sorted
//   d_in[3] = num_segments (scalar, unused; nrows = out_size / 128)
// ---------------------------------------------------------------------------

#define MAX_ROWS 131072
#define D_FEAT   128

__device__ int g_offsets[MAX_ROWS + 1];
__device__ int g_is64;

// ---- dtype detection: neigh_ids is uniform-random in [0, N_NODES), so for
// int64 little-endian every odd 32-bit word is 0; for int32 essentially never.
__global__ void detect_kernel(const void* neigh) {
    if (threadIdx.x == 0 && blockIdx.x == 0) {
        const unsigned* w = (const unsigned*)neigh;
        int zeros = 0;
#pragma unroll
        for (int i = 0; i < 64; i++) zeros += (w[2 * i + 1] == 0u);
        g_is64 = (zeros >= 60) ? 1 : 0;
    }
}

// ---- prefill offsets with E (handles trailing empty rows)
__global__ void prefill_kernel(int E, int nrows) {
    int q = blockIdx.x * blockDim.x + threadIdx.x;
    if (q <= nrows) g_offsets[q] = E;
}

template <typename IdxT>
__device__ __forceinline__ int row_at(const void* p, int i) {
    return (int)((const IdxT*)p)[i];
}

// ---- segment boundaries from sorted row_ids
__global__ void bounds_kernel(const void* rows_v, int E) {
    int i = blockIdx.x * blockDim.x + threadIdx.x;
    if (i >= E) return;
    const bool is64 = (g_is64 != 0);
    int r  = is64 ? row_at<long long>(rows_v, i) : row_at<int>(rows_v, i);
    int rp = (i == 0) ? -1
                      : (is64 ? row_at<long long>(rows_v, i - 1)
                              : row_at<int>(rows_v, i - 1));
    // all rows in (rp, r] start at edge i (covers gaps / leading empties)
    for (int q = rp + 1; q <= r; q++) g_offsets[q] = i;
}

// ---- main gather+mean: one warp per row, lane owns float4 (4 dims)
template <typename IdxT>
__device__ __forceinline__ void aggregate_row(const float4* __restrict__ feats,
                                              const IdxT* __restrict__ neigh,
                                              int row, int lane, int lo, int hi,
                                              float4* __restrict__ out) {
    float x = 0.f, y = 0.f, z = 0.f, w = 0.f;
    int e = lo;
    for (; e + 4 <= hi; e += 4) {
        size_t n0 = (size_t)neigh[e + 0];
        size_t n1 = (size_t)neigh[e + 1];
        size_t n2 = (size_t)neigh[e + 2];
        size_t n3 = (size_t)neigh[e + 3];
        float4 a = __ldg(feats + n0 * (D_FEAT / 4) + lane);
        float4 b = __ldg(feats + n1 * (D_FEAT / 4) + lane);
        float4 c = __ldg(feats + n2 * (D_FEAT / 4) + lane);
        float4 d = __ldg(feats + n3 * (D_FEAT / 4) + lane);
        x += (a.x + b.x) + (c.x + d.x);
        y += (a.y + b.y) + (c.y + d.y);
        z += (a.z + b.z) + (c.z + d.z);
        w += (a.w + b.w) + (c.w + d.w);
    }
    for (; e < hi; e++) {
        size_t n = (size_t)neigh[e];
        float4 a = __ldg(feats + n * (D_FEAT / 4) + lane);
        x += a.x; y += a.y; z += a.z; w += a.w;
    }
    int cnt = hi - lo;
    float inv = 1.0f / (float)(cnt > 0 ? cnt : 1);
    float4 r4 = make_float4(x * inv, y * inv, z * inv, w * inv);
    out[(size_t)row * (D_FEAT / 4) + lane] = r4;
}

__global__ __launch_bounds__(256) void agg_kernel(const float4* __restrict__ feats,
                                                  const void* __restrict__ neigh_v,
                                                  int nrows,
                                                  float4* __restrict__ out) {
    int gwarp = (blockIdx.x * blockDim.x + threadIdx.x) >> 5;
    int lane  = threadIdx.x & 31;
    if (gwarp >= nrows) return;
    int lo = g_offsets[gwarp];
    int hi = g_offsets[gwarp + 1];
    if (g_is64)
        aggregate_row<long long>(feats, (const long long*)neigh_v, gwarp, lane, lo, hi, out);
    else
        aggregate_row<int>(feats, (const int*)neigh_v, gwarp, lane, lo, hi, out);
}

extern "C" void kernel_launch(void* const* d_in, const int* in_sizes, int n_in,
                              void* d_out, int out_size) {
    const float* feats = (const float*)d_in[0];
    const void*  neigh = d_in[1];
    const void*  rows  = d_in[2];
    int E     = in_sizes[1];
    int nrows = out_size / D_FEAT;

    detect_kernel<<<1, 32>>>(neigh);
    prefill_kernel<<<(nrows + 256) / 256, 256>>>(E, nrows);
    bounds_kernel<<<(E + 255) / 256, 256>>>(rows, E);

    int total_threads = nrows * 32;
    agg_kernel<<<(total_threads + 255) / 256, 256>>>(
        (const float4*)feats, neigh, nrows, (float4*)d_out);
}